// round 1
// baseline (speedup 1.0000x reference)
#include <cuda_runtime.h>
#include <cuda_bf16.h>

#define LSE_EPS 1e-5f

// Folded parameters: W1f[16] (o-major, o*4+c), t1[4], W2f[32] (o*4+c), t2[8]
__device__ float g_params[60];

__global__ void lse_fold_params(const float* __restrict__ W1, const float* __restrict__ g1,
                                const float* __restrict__ b1, const float* __restrict__ m1,
                                const float* __restrict__ v1,
                                const float* __restrict__ W2, const float* __restrict__ g2,
                                const float* __restrict__ b2, const float* __restrict__ m2,
                                const float* __restrict__ v2) {
    int i = threadIdx.x;
    if (i < 4) {
        float s = g1[i] * rsqrtf(v1[i] + LSE_EPS);
        #pragma unroll
        for (int c = 0; c < 4; c++) g_params[i * 4 + c] = W1[i * 4 + c] * s;
        g_params[16 + i] = b1[i] - m1[i] * s;
    }
    if (i < 8) {
        float s = g2[i] * rsqrtf(v2[i] + LSE_EPS);
        #pragma unroll
        for (int c = 0; c < 4; c++) g_params[20 + i * 4 + c] = W2[i * 4 + c] * s;
        g_params[52 + i] = b2[i] - m2[i] * s;
    }
}

// One thread handles one (b,n): 16 neighbors.
// Reads: 3 coord floats, 12x float4 neighbors (192B contiguous, 16B aligned).
// Writes: 32x float4 outputs (512B contiguous).
__global__ __launch_bounds__(256) void lse_main(const float* __restrict__ coords,
                                                const float* __restrict__ nbr,
                                                float* __restrict__ out,
                                                int total_bn) {
    __shared__ float sp[60];
    if (threadIdx.x < 60) sp[threadIdx.x] = g_params[threadIdx.x];
    __syncthreads();

    int bn = blockIdx.x * blockDim.x + threadIdx.x;
    if (bn >= total_bn) return;

    // Register-resident folded params
    float W1f[16], t1[4], W2f[32], t2[8];
    #pragma unroll
    for (int i = 0; i < 16; i++) W1f[i] = sp[i];
    #pragma unroll
    for (int i = 0; i < 4; i++) t1[i] = sp[16 + i];
    #pragma unroll
    for (int i = 0; i < 32; i++) W2f[i] = sp[20 + i];
    #pragma unroll
    for (int i = 0; i < 8; i++) t2[i] = sp[52 + i];

    size_t cb = (size_t)bn * 3;
    float cx = coords[cb + 0];
    float cy = coords[cb + 1];
    float cz = coords[cb + 2];

    const float4* nb = reinterpret_cast<const float4*>(nbr + (size_t)bn * 48);
    float4*       ob = reinterpret_cast<float4*>(out + (size_t)bn * 128);

    #pragma unroll
    for (int it = 0; it < 4; it++) {
        float4 a = nb[it * 3 + 0];
        float4 b = nb[it * 3 + 1];
        float4 c = nb[it * 3 + 2];
        float n[12] = {a.x, a.y, a.z, a.w, b.x, b.y, b.z, b.w, c.x, c.y, c.z, c.w};

        #pragma unroll
        for (int k = 0; k < 4; k++) {
            float rx = n[k * 3 + 0] - cx;
            float ry = n[k * 3 + 1] - cy;
            float rz = n[k * 3 + 2] - cz;
            float d  = sqrtf(fmaf(rx, rx, fmaf(ry, ry, rz * rz)));

            float h[4];
            #pragma unroll
            for (int o = 0; o < 4; o++) {
                float acc = t1[o];
                acc = fmaf(rx, W1f[o * 4 + 0], acc);
                acc = fmaf(ry, W1f[o * 4 + 1], acc);
                acc = fmaf(rz, W1f[o * 4 + 2], acc);
                acc = fmaf(d,  W1f[o * 4 + 3], acc);
                h[o] = fmaxf(acc, 0.0f);
            }

            float r[8];
            #pragma unroll
            for (int o = 0; o < 8; o++) {
                float acc = t2[o];
                acc = fmaf(h[0], W2f[o * 4 + 0], acc);
                acc = fmaf(h[1], W2f[o * 4 + 1], acc);
                acc = fmaf(h[2], W2f[o * 4 + 2], acc);
                acc = fmaf(h[3], W2f[o * 4 + 3], acc);
                r[o] = fmaxf(acc, 0.0f);
            }

            ob[(it * 4 + k) * 2 + 0] = make_float4(r[0], r[1], r[2], r[3]);
            ob[(it * 4 + k) * 2 + 1] = make_float4(r[4], r[5], r[6], r[7]);
        }
    }
}

extern "C" void kernel_launch(void* const* d_in, const int* in_sizes, int n_in,
                              void* d_out, int out_size) {
    const float* coords = (const float*)d_in[0];   // (B,N,3)
    const float* nbr    = (const float*)d_in[1];   // (B,N,K,3)
    const float* W1 = (const float*)d_in[2];
    const float* g1 = (const float*)d_in[3];
    const float* b1 = (const float*)d_in[4];
    const float* m1 = (const float*)d_in[5];
    const float* v1 = (const float*)d_in[6];
    const float* W2 = (const float*)d_in[7];
    const float* g2 = (const float*)d_in[8];
    const float* b2 = (const float*)d_in[9];
    const float* m2 = (const float*)d_in[10];
    const float* v2 = (const float*)d_in[11];
    float* out = (float*)d_out;

    int total_bn = in_sizes[0] / 3;   // B*N = 131072

    lse_fold_params<<<1, 32>>>(W1, g1, b1, m1, v1, W2, g2, b2, m2, v2);

    int threads = 256;
    int blocks = (total_bn + threads - 1) / threads;
    lse_main<<<blocks, threads>>>(coords, nbr, out, total_bn);
}

// round 2
// speedup vs baseline: 1.3355x; 1.3355x over previous
#include <cuda_runtime.h>
#include <cuda_bf16.h>

#define LSE_EPS 1e-5f
#define LSE_ITER 4

// Folded parameters: W1f[16] (o*4+c), t1[4] @16, W2f[32] @20 (o*4+c), t2[8] @52
__device__ float g_params[60];

__global__ void lse_fold_params(const float* __restrict__ W1, const float* __restrict__ g1,
                                const float* __restrict__ b1, const float* __restrict__ m1,
                                const float* __restrict__ v1,
                                const float* __restrict__ W2, const float* __restrict__ g2,
                                const float* __restrict__ b2, const float* __restrict__ m2,
                                const float* __restrict__ v2) {
    int i = threadIdx.x;
    if (i < 4) {
        float s = g1[i] * rsqrtf(v1[i] + LSE_EPS);
        #pragma unroll
        for (int c = 0; c < 4; c++) g_params[i * 4 + c] = W1[i * 4 + c] * s;
        g_params[16 + i] = b1[i] - m1[i] * s;
    }
    if (i < 8) {
        float s = g2[i] * rsqrtf(v2[i] + LSE_EPS);
        #pragma unroll
        for (int c = 0; c < 4; c++) g_params[20 + i * 4 + c] = W2[i * 4 + c] * s;
        g_params[52 + i] = b2[i] - m2[i] * s;
    }
}

// Thread-per-neighbor layout (4 neighbors per thread, strided by blockDim so
// every iteration keeps warp-dense global access):
//   loads:  3 scalar floats/lane, lane stride 12B  -> ~dense
//   stores: 2x STG.128/lane, lane stride 32B       -> 2x line inflation (acceptable)
__global__ __launch_bounds__(256) void lse_main(const float* __restrict__ coords,
                                                const float* __restrict__ nbr,
                                                float* __restrict__ out,
                                                int total_nb) {
    __shared__ float sp[60];
    if (threadIdx.x < 60) sp[threadIdx.x] = g_params[threadIdx.x];
    __syncthreads();

    // Register-resident folded params, amortized over LSE_ITER neighbors
    float W1f[16], t1[4], W2f[32], t2[8];
    #pragma unroll
    for (int i = 0; i < 16; i++) W1f[i] = sp[i];
    #pragma unroll
    for (int i = 0; i < 4; i++) t1[i] = sp[16 + i];
    #pragma unroll
    for (int i = 0; i < 32; i++) W2f[i] = sp[20 + i];
    #pragma unroll
    for (int i = 0; i < 8; i++) t2[i] = sp[52 + i];

    int base = blockIdx.x * (blockDim.x * LSE_ITER) + threadIdx.x;

    #pragma unroll
    for (int it = 0; it < LSE_ITER; it++) {
        int g = base + it * 256;           // global neighbor id
        if (g < total_nb) {
            int bn = g >> 4;               // point id (16 neighbors per point)

            // broadcast-friendly center loads (2 distinct points per warp -> L1 hits)
            float cx = __ldg(coords + bn * 3 + 0);
            float cy = __ldg(coords + bn * 3 + 1);
            float cz = __ldg(coords + bn * 3 + 2);

            // dense neighbor loads: warp covers 384B contiguous
            float nx = __ldg(nbr + (size_t)g * 3 + 0);
            float ny = __ldg(nbr + (size_t)g * 3 + 1);
            float nz = __ldg(nbr + (size_t)g * 3 + 2);

            float rx = nx - cx;
            float ry = ny - cy;
            float rz = nz - cz;
            float d  = sqrtf(fmaf(rx, rx, fmaf(ry, ry, rz * rz)));

            float h[4];
            #pragma unroll
            for (int o = 0; o < 4; o++) {
                float acc = t1[o];
                acc = fmaf(rx, W1f[o * 4 + 0], acc);
                acc = fmaf(ry, W1f[o * 4 + 1], acc);
                acc = fmaf(rz, W1f[o * 4 + 2], acc);
                acc = fmaf(d,  W1f[o * 4 + 3], acc);
                h[o] = fmaxf(acc, 0.0f);
            }

            float r[8];
            #pragma unroll
            for (int o = 0; o < 8; o++) {
                float acc = t2[o];
                acc = fmaf(h[0], W2f[o * 4 + 0], acc);
                acc = fmaf(h[1], W2f[o * 4 + 1], acc);
                acc = fmaf(h[2], W2f[o * 4 + 2], acc);
                acc = fmaf(h[3], W2f[o * 4 + 3], acc);
                r[o] = fmaxf(acc, 0.0f);
            }

            float4* ob = reinterpret_cast<float4*>(out + (size_t)g * 8);
            ob[0] = make_float4(r[0], r[1], r[2], r[3]);
            ob[1] = make_float4(r[4], r[5], r[6], r[7]);
        }
    }
}

extern "C" void kernel_launch(void* const* d_in, const int* in_sizes, int n_in,
                              void* d_out, int out_size) {
    const float* coords = (const float*)d_in[0];   // (B,N,3)
    const float* nbr    = (const float*)d_in[1];   // (B,N,K,3)
    const float* W1 = (const float*)d_in[2];
    const float* g1 = (const float*)d_in[3];
    const float* b1 = (const float*)d_in[4];
    const float* m1 = (const float*)d_in[5];
    const float* v1 = (const float*)d_in[6];
    const float* W2 = (const float*)d_in[7];
    const float* g2 = (const float*)d_in[8];
    const float* b2 = (const float*)d_in[9];
    const float* m2 = (const float*)d_in[10];
    const float* v2 = (const float*)d_in[11];
    float* out = (float*)d_out;

    int total_nb = (in_sizes[0] / 3) * 16;   // B*N*K = 2,097,152

    lse_fold_params<<<1, 32>>>(W1, g1, b1, m1, v1, W2, g2, b2, m2, v2);

    int threads = 256;
    int per_block = threads * LSE_ITER;
    int blocks = (total_nb + per_block - 1) / per_block;
    lse_main<<<blocks, threads>>>(coords, nbr, out, total_nb);
}